// round 4
// baseline (speedup 1.0000x reference)
#include <cuda_runtime.h>
#include <cuda_bf16.h>
#include <stdint.h>

#define NNODES   50000
#define NTILES   391
#define LN_EPS   1e-5f

// ---- smem layout (bytes) ----
#define OFF_BIAS 0
#define OFF_LNS  1024
#define OFF_LNO  2048
#define OFF_PS   3072      // [4][128] f32
#define OFF_PQ   5120
#define OFF_MU   7168
#define OFF_RS   7680
#define OFF_A    8192      // 2 bufs x (2 splits x 128 rows x 80B) = 2 x 20480
#define OFF_B    49152     // 2 bufs x (2 splits x 256 rows x 80B) = 2 x 40960
#define SMEM_TOTAL 131072

// ---- device scratch (no allocation allowed) ----
__device__ float g_x0[(size_t)NNODES * 256];
__device__ float g_x1[(size_t)NNODES * 256];
__device__ float g_ns[(size_t)NNODES * 256];
// [step(3)][chunk(16)][split(2)] x (256 n x 32 k) bf16, n-major rows of 64B
__device__ __nv_bfloat16 g_Wb[3 * 16 * 2 * 8192];

// ---------------- helpers ----------------
__device__ __forceinline__ uint32_t smem_u32(const void* p) {
    uint32_t a;
    asm("{ .reg .u64 t; cvta.to.shared.u64 t, %1; cvt.u32.u64 %0, t; }" : "=r"(a) : "l"(p));
    return a;
}
__device__ __forceinline__ void ldsm4(uint32_t* r, uint32_t addr) {
    asm volatile("ldmatrix.sync.aligned.m8n8.x4.shared.b16 {%0,%1,%2,%3}, [%4];"
                 : "=r"(r[0]), "=r"(r[1]), "=r"(r[2]), "=r"(r[3]) : "r"(addr));
}
__device__ __forceinline__ void mma_bf16(float* c, const uint32_t* a, const uint32_t* b) {
    asm volatile(
        "mma.sync.aligned.m16n8k16.row.col.f32.bf16.bf16.f32 "
        "{%0,%1,%2,%3}, {%4,%5,%6,%7}, {%8,%9}, {%0,%1,%2,%3};"
        : "+f"(c[0]), "+f"(c[1]), "+f"(c[2]), "+f"(c[3])
        : "r"(a[0]), "r"(a[1]), "r"(a[2]), "r"(a[3]), "r"(b[0]), "r"(b[1]));
}
__device__ __forceinline__ uint32_t pk(__nv_bfloat16 a, __nv_bfloat16 b) {
    __nv_bfloat162 t; t.x = a; t.y = b;
    return *reinterpret_cast<uint32_t*>(&t);
}
__device__ __forceinline__ void split2(float f0, float f1, uint32_t& hw, uint32_t& lw) {
    __nv_bfloat16 h0 = __float2bfloat16(f0), h1 = __float2bfloat16(f1);
    float l0 = f0 - __bfloat162float(h0), l1 = f1 - __bfloat162float(h1);
    hw = pk(h0, h1);
    lw = pk(__float2bfloat16(l0), __float2bfloat16(l1));
}

// ============ prep: bf16 hi/lo, transposed (n-major), residual folded ============
__global__ void prep_kernel(const float* __restrict__ Ws, const float* __restrict__ Wn) {
    int bi = blockIdx.x;               // 0..47 = step*16 + chunk
    int step = bi >> 4, chunk = bi & 15;
    int n = threadIdx.x;               // 0..255
    size_t base = (size_t)(step * 16 + chunk) * 2 * 8192;
#pragma unroll 4
    for (int k = 0; k < 32; k++) {
        int kg = chunk * 32 + k;
        float w;
        if (kg < 256)
            w = Ws[step * 65536 + kg * 256 + n] + (kg == n ? 1.0f : 0.0f);
        else
            w = Wn[step * 65536 + (kg - 256) * 256 + n] * (1.0f / 6.0f);
        __nv_bfloat16 h = __float2bfloat16(w);
        float rem = w - __bfloat162float(h);
        g_Wb[base + n * 32 + k]        = h;
        g_Wb[base + 8192 + n * 32 + k] = __float2bfloat16(rem);
    }
}

// ============ nsum: neighbor sum (mean folded into Wn already) ============
__global__ void __launch_bounds__(256) nsum_kernel(const float* __restrict__ xin,
                                                   float* __restrict__ out,
                                                   const int* __restrict__ nbr) {
    __shared__ int nb[4][6];
    int tid = threadIdx.x;
    int node0 = blockIdx.x * 4;
    if (tid < 24) nb[tid / 6][tid % 6] = nbr[(node0 + tid / 6) * 6 + tid % 6];
    __syncthreads();
    int nl = tid >> 6, seg = tid & 63;
    float4 acc = make_float4(0.f, 0.f, 0.f, 0.f);
#pragma unroll
    for (int j = 0; j < 6; j++) {
        const float4 v = *(const float4*)(xin + (size_t)nb[nl][j] * 256 + seg * 4);
        acc.x += v.x; acc.y += v.y; acc.z += v.z; acc.w += v.w;
    }
    *(float4*)(out + (size_t)(node0 + nl) * 256 + seg * 4) = acc;
}

// ============ main fused GEMM+LN+ReLU ============
__global__ void __launch_bounds__(512, 1)
gemm_kernel(const float* __restrict__ xin, const float* __restrict__ nsum,
            float* __restrict__ xout,
            const float* __restrict__ bs, const float* __restrict__ bn,
            const float* __restrict__ lns, const float* __restrict__ lno, int step) {
    extern __shared__ char smem[];
    const int tid = threadIdx.x, lid = tid & 31, wid = tid >> 5;
    const int wm = wid >> 2, wn = wid & 3;    // 4x4 warp grid, tiles 32x64
    const int tile = blockIdx.x;

    float* bias_s = (float*)(smem + OFF_BIAS);
    float* lns_s  = (float*)(smem + OFF_LNS);
    float* lno_s  = (float*)(smem + OFF_LNO);
    float* ps     = (float*)(smem + OFF_PS);
    float* pq     = (float*)(smem + OFF_PQ);
    float* mu_s   = (float*)(smem + OFF_MU);
    float* rs_s   = (float*)(smem + OFF_RS);
    char* A_s = smem + OFF_A;
    char* B_s = smem + OFF_B;
    const uint32_t sbA = smem_u32(A_s), sbB = smem_u32(B_s);

    if (tid < 256) {
        bias_s[tid] = bs[step * 256 + tid] + bn[step * 256 + tid];
        lns_s[tid]  = lns[step * 256 + tid];
        lno_s[tid]  = lno[step * 256 + tid];
    }

    // ---- produce mappings ----
    const int prow = tid >> 2, pseg = tid & 3;      // A: 128 rows x 4 k-segments(8)
    int pnode = tile * 128 + prow; if (pnode >= NNODES) pnode = 0;
    const int bsplit = tid >> 8, bnrow = tid & 255; // B: 2 splits x 256 n-rows

    float acc[2][8][4];
#pragma unroll
    for (int i = 0; i < 2; i++)
#pragma unroll
        for (int j = 0; j < 8; j++)
#pragma unroll
            for (int k = 0; k < 4; k++) acc[i][j][k] = 0.f;

    const uint32_t a_lane = (uint32_t)((lid & 15) * 80 + (lid >> 4) * 16);
    const uint32_t b_lane = (uint32_t)(((lid & 7) + ((lid >> 1) & 8)) * 80 + ((lid << 1) & 16));

#define LOAD_AB(c)                                                                     \
    {                                                                                  \
        const float* asrc = ((c) < 8 ? xin : nsum) + (size_t)pnode * 256 +             \
                            ((c) & 7) * 32 + pseg * 8;                                 \
        av0 = *(const float4*)asrc; av1 = *(const float4*)(asrc + 4);                  \
        const uint4* bsrc = (const uint4*)g_Wb +                                       \
                            ((size_t)((step * 16 + (c)) * 2 + bsplit)) * 1024 +        \
                            bnrow * 4;                                                 \
        w0 = bsrc[0]; w1 = bsrc[1]; w2 = bsrc[2]; w3 = bsrc[3];                        \
    }
#define STORE_AB(buf)                                                                  \
    {                                                                                  \
        uint4 hh, ll;                                                                  \
        split2(av0.x, av0.y, hh.x, ll.x); split2(av0.z, av0.w, hh.y, ll.y);            \
        split2(av1.x, av1.y, hh.z, ll.z); split2(av1.z, av1.w, hh.w, ll.w);            \
        char* ad = A_s + (buf) * 20480 + prow * 80 + pseg * 16;                        \
        *(uint4*)ad = hh; *(uint4*)(ad + 10240) = ll;                                  \
        char* bd = B_s + (buf) * 40960 + bsplit * 20480 + bnrow * 80;                  \
        *(uint4*)(bd) = w0; *(uint4*)(bd + 16) = w1;                                   \
        *(uint4*)(bd + 32) = w2; *(uint4*)(bd + 48) = w3;                              \
    }

    {   // prologue: chunk 0
        float4 av0, av1; uint4 w0, w1, w2, w3;
        LOAD_AB(0)
        STORE_AB(0)
    }
    __syncthreads();

    for (int c = 0; c < 16; c++) {
        const int buf = c & 1;
        float4 av0, av1; uint4 w0, w1, w2, w3;
        if (c < 15) LOAD_AB(c + 1)

        // ---- compute chunk c: 2 ksteps x 3 split-products ----
        const uint32_t abase = sbA + buf * 20480 + wm * 32 * 80 + a_lane;
        const uint32_t bbase = sbB + buf * 40960 + wn * 64 * 80 + b_lane;
#pragma unroll
        for (int s = 0; s < 2; s++) {
            uint32_t ah[2][4], al[2][4], bb[4][4];
#pragma unroll
            for (int i = 0; i < 2; i++) {
                ldsm4(ah[i], abase + i * 16 * 80 + s * 32);
                ldsm4(al[i], abase + 10240 + i * 16 * 80 + s * 32);
            }
#pragma unroll
            for (int p = 0; p < 4; p++) ldsm4(bb[p], bbase + p * 16 * 80 + s * 32);
#pragma unroll
            for (int i = 0; i < 2; i++)
#pragma unroll
                for (int j = 0; j < 8; j++)
                    mma_bf16(acc[i][j], ah[i], &bb[j >> 1][(j & 1) * 2]);
#pragma unroll
            for (int i = 0; i < 2; i++)
#pragma unroll
                for (int j = 0; j < 8; j++)
                    mma_bf16(acc[i][j], al[i], &bb[j >> 1][(j & 1) * 2]);
#pragma unroll
            for (int p = 0; p < 4; p++) ldsm4(bb[p], bbase + 20480 + p * 16 * 80 + s * 32);
#pragma unroll
            for (int i = 0; i < 2; i++)
#pragma unroll
                for (int j = 0; j < 8; j++)
                    mma_bf16(acc[i][j], ah[i], &bb[j >> 1][(j & 1) * 2]);
        }

        if (c < 15) STORE_AB(buf ^ 1)
        __syncthreads();
    }

    // ---- epilogue: bias, LN stats, LN+ReLU, store ----
#pragma unroll
    for (int i = 0; i < 2; i++) {
        float sa = 0.f, qa = 0.f, sb2 = 0.f, qb = 0.f;
#pragma unroll
        for (int j = 0; j < 8; j++) {
            int c0 = wn * 64 + j * 8 + (lid & 3) * 2;
            float b0 = bias_s[c0], b1 = bias_s[c0 + 1];
            float v0 = acc[i][j][0] + b0, v1 = acc[i][j][1] + b1;
            float v2 = acc[i][j][2] + b0, v3 = acc[i][j][3] + b1;
            acc[i][j][0] = v0; acc[i][j][1] = v1; acc[i][j][2] = v2; acc[i][j][3] = v3;
            sa += v0 + v1; qa += v0 * v0 + v1 * v1;
            sb2 += v2 + v3; qb += v2 * v2 + v3 * v3;
        }
#pragma unroll
        for (int off = 1; off < 4; off <<= 1) {
            sa  += __shfl_xor_sync(0xFFFFFFFFu, sa, off);
            qa  += __shfl_xor_sync(0xFFFFFFFFu, qa, off);
            sb2 += __shfl_xor_sync(0xFFFFFFFFu, sb2, off);
            qb  += __shfl_xor_sync(0xFFFFFFFFu, qb, off);
        }
        if ((lid & 3) == 0) {
            int ra = wm * 32 + i * 16 + (lid >> 2);
            ps[wn * 128 + ra] = sa;     pq[wn * 128 + ra] = qa;
            ps[wn * 128 + ra + 8] = sb2; pq[wn * 128 + ra + 8] = qb;
        }
    }
    __syncthreads();
    if (tid < 128) {
        float s = ps[tid] + ps[128 + tid] + ps[256 + tid] + ps[384 + tid];
        float q = pq[tid] + pq[128 + tid] + pq[256 + tid] + pq[384 + tid];
        float mu = s * (1.0f / 256.0f);
        float var = q * (1.0f / 256.0f) - mu * mu;
        mu_s[tid] = mu;
        rs_s[tid] = rsqrtf(var + LN_EPS);
    }
    __syncthreads();

#pragma unroll
    for (int i = 0; i < 2; i++) {
        int ra = wm * 32 + i * 16 + (lid >> 2);
        int na = tile * 128 + ra, nb2 = na + 8;
        float mua = mu_s[ra],     rsa = rs_s[ra];
        float mub = mu_s[ra + 8], rsb = rs_s[ra + 8];
#pragma unroll
        for (int j = 0; j < 8; j++) {
            int c0 = wn * 64 + j * 8 + (lid & 3) * 2;
            float s0 = lns_s[c0], s1 = lns_s[c0 + 1];
            float o0 = lno_s[c0], o1 = lno_s[c0 + 1];
            if (na < NNODES) {
                float2 y;
                y.x = fmaxf(fmaf((acc[i][j][0] - mua) * rsa, s0, o0), 0.f);
                y.y = fmaxf(fmaf((acc[i][j][1] - mua) * rsa, s1, o1), 0.f);
                *(float2*)(xout + (size_t)na * 256 + c0) = y;
            }
            if (nb2 < NNODES) {
                float2 y;
                y.x = fmaxf(fmaf((acc[i][j][2] - mub) * rsb, s0, o0), 0.f);
                y.y = fmaxf(fmaf((acc[i][j][3] - mub) * rsb, s1, o1), 0.f);
                *(float2*)(xout + (size_t)nb2 * 256 + c0) = y;
            }
        }
    }
}

// ================= launch ========================
extern "C" void kernel_launch(void* const* d_in, const int* in_sizes, int n_in,
                              void* d_out, int out_size) {
    const float* x0  = (const float*)d_in[0];
    const float* Ws  = (const float*)d_in[1];
    const float* bsp = (const float*)d_in[2];
    const float* Wn  = (const float*)d_in[3];
    const float* bnp = (const float*)d_in[4];
    const float* lns = (const float*)d_in[5];
    const float* lno = (const float*)d_in[6];
    const int*   nbr = (const int*)d_in[7];
    float* out = (float*)d_out;

    float *px0, *px1, *pns;
    cudaGetSymbolAddress((void**)&px0, g_x0);
    cudaGetSymbolAddress((void**)&px1, g_x1);
    cudaGetSymbolAddress((void**)&pns, g_ns);

    cudaFuncSetAttribute(gemm_kernel, cudaFuncAttributeMaxDynamicSharedMemorySize, SMEM_TOTAL);

    prep_kernel<<<48, 256>>>(Ws, Wn);

    nsum_kernel<<<NNODES / 4, 256>>>(x0, pns, nbr);
    gemm_kernel<<<NTILES, 512, SMEM_TOTAL>>>(x0, pns, px0, bsp, bnp, lns, lno, 0);

    nsum_kernel<<<NNODES / 4, 256>>>(px0, pns, nbr);
    gemm_kernel<<<NTILES, 512, SMEM_TOTAL>>>(px0, pns, px1, bsp, bnp, lns, lno, 1);

    nsum_kernel<<<NNODES / 4, 256>>>(px1, pns, nbr);
    gemm_kernel<<<NTILES, 512, SMEM_TOTAL>>>(px1, pns, out, bsp, bnp, lns, lno, 2);
}